// round 1
// baseline (speedup 1.0000x reference)
#include <cuda_runtime.h>
#include <cuda_bf16.h>

// ---------------------------------------------------------------------------
// VQ-VAE forward, fp32 baseline.
// Shapes: B=4096, COND=256, E=128, L=16 (L*E=2048), Kcb=2048, P=256.
// Outputs concatenated in d_out: recon[4096*256], encoded[4096*2048],
// discrete[65536*2048], quantized[4096*2048].
// ---------------------------------------------------------------------------

#define BQ 4096
#define LE 2048
#define EE 128
#define KCB 2048
#define NROWS 65536   // B*L

// scratch (device globals; allocation-free rule)
__device__ float g_x1[BQ * EE];          // 2 MB   (also reused as y3)
__device__ float g_a [BQ * LE];          // 32 MB
__device__ float g_b [BQ * LE];          // 32 MB
__device__ float g_cbT[EE * KCB];        // 1 MB
__device__ float g_cbnorm[KCB];

__device__ __forceinline__ float lrelu(float v) {
    // negative_slope = 0.2, slope < 1 so max(v, 0.2v) is exact
    return fmaxf(v, 0.2f * v);
}

// ---------------------------------------------------------------------------
// codebook prep: transpose [2048,128] -> [128,2048] and row norms
// ---------------------------------------------------------------------------
__global__ void cbprep_kernel(const float* __restrict__ cb,
                              float* __restrict__ cbT,
                              float* __restrict__ cbnorm) {
    int n = blockIdx.x;       // 0..2047
    int e = threadIdx.x;      // 0..127
    float v = cb[n * EE + e];
    cbT[e * KCB + n] = v;
    float s = v * v;
    #pragma unroll
    for (int off = 16; off > 0; off >>= 1)
        s += __shfl_xor_sync(0xFFFFFFFFu, s, off);
    __shared__ float ws[4];
    if ((e & 31) == 0) ws[e >> 5] = s;
    __syncthreads();
    if (e == 0) cbnorm[n] = ws[0] + ws[1] + ws[2] + ws[3];
}

// ---------------------------------------------------------------------------
// zero fill (for the one-hot `discrete` region)
// ---------------------------------------------------------------------------
__global__ void zero_kernel(float4* __restrict__ p, long n4) {
    long i = (long)blockIdx.x * blockDim.x + threadIdx.x;
    long stride = (long)gridDim.x * blockDim.x;
    float4 z = make_float4(0.f, 0.f, 0.f, 0.f);
    for (; i < n4; i += stride) p[i] = z;
}

// ---------------------------------------------------------------------------
// Fused Dense + LeakyReLU:  C[M,N] = lrelu(A[M,K] @ W[K,N] + bias)
// 128x128 block tile, BK=8, 8x8 per-thread (2x2 fragments of 4), 256 threads.
// Requires M%128==0, N%128==0 or N in {128,256,...}, K%8==0.
// ---------------------------------------------------------------------------
__global__ __launch_bounds__(256, 2) void dense_lrelu_kernel(
    const float* __restrict__ A, const float* __restrict__ W,
    const float* __restrict__ bias, float* __restrict__ C,
    int M, int N, int K)
{
    __shared__ float As[8][128];
    __shared__ float Bs[8][128];

    int tid = threadIdx.x;
    int tx = tid & 15;        // 0..15
    int ty = tid >> 4;        // 0..15
    int bm = blockIdx.y * 128;
    int bn = blockIdx.x * 128;

    int arow = tid >> 1;          // 0..127
    int acol = (tid & 1) * 4;     // 0 or 4
    int wrow = tid >> 5;          // 0..7
    int wcol = (tid & 31) * 4;    // 0..124

    float acc[8][8];
    #pragma unroll
    for (int i = 0; i < 8; i++)
        #pragma unroll
        for (int j = 0; j < 8; j++) acc[i][j] = 0.f;

    const float* Aptr = A + (long)(bm + arow) * K + acol;
    const float* Wptr = W + (long)wrow * N + bn + wcol;

    for (int k0 = 0; k0 < K; k0 += 8) {
        float4 av = *(const float4*)(Aptr + k0);
        float4 wv = *(const float4*)(Wptr + (long)k0 * N);
        As[acol + 0][arow] = av.x;
        As[acol + 1][arow] = av.y;
        As[acol + 2][arow] = av.z;
        As[acol + 3][arow] = av.w;
        *(float4*)&Bs[wrow][wcol] = wv;
        __syncthreads();
        #pragma unroll
        for (int kk = 0; kk < 8; kk++) {
            float a0[4], a1[4], b0[4], b1[4];
            *(float4*)a0 = *(const float4*)&As[kk][ty * 4];
            *(float4*)a1 = *(const float4*)&As[kk][64 + ty * 4];
            *(float4*)b0 = *(const float4*)&Bs[kk][tx * 4];
            *(float4*)b1 = *(const float4*)&Bs[kk][64 + tx * 4];
            #pragma unroll
            for (int i = 0; i < 4; i++)
                #pragma unroll
                for (int j = 0; j < 4; j++) {
                    acc[i    ][j    ] += a0[i] * b0[j];
                    acc[i    ][j + 4] += a0[i] * b1[j];
                    acc[i + 4][j    ] += a1[i] * b0[j];
                    acc[i + 4][j + 4] += a1[i] * b1[j];
                }
        }
        __syncthreads();
    }

    float bb0[4], bb1[4];
    #pragma unroll
    for (int j = 0; j < 4; j++) {
        bb0[j] = bias[bn + tx * 4 + j];
        bb1[j] = bias[bn + 64 + tx * 4 + j];
    }
    #pragma unroll
    for (int i = 0; i < 8; i++) {
        int r = bm + ((i < 4) ? (ty * 4 + i) : (64 + ty * 4 + i - 4));
        float4 o;
        o.x = lrelu(acc[i][0] + bb0[0]);
        o.y = lrelu(acc[i][1] + bb0[1]);
        o.z = lrelu(acc[i][2] + bb0[2]);
        o.w = lrelu(acc[i][3] + bb0[3]);
        *(float4*)&C[(long)r * N + bn + tx * 4] = o;
        o.x = lrelu(acc[i][4] + bb1[0]);
        o.y = lrelu(acc[i][5] + bb1[1]);
        o.z = lrelu(acc[i][6] + bb1[2]);
        o.w = lrelu(acc[i][7] + bb1[3]);
        *(float4*)&C[(long)r * N + bn + 64 + tx * 4] = o;
    }
}

// ---------------------------------------------------------------------------
// VQ kernel: for each of 128 rows per block, compute scores
//   s(n) = ||c_n||^2 - 2 * x . c_n   over all 2048 codewords,
// track (min, argmin) with jnp.argmin (first-index) tie semantics, then write
// quantized rows (codebook gather) and scatter 1.0 into pre-zeroed discrete.
// ---------------------------------------------------------------------------
__global__ __launch_bounds__(256, 2) void vq_kernel(
    const float* __restrict__ flat,      // [65536,128]
    const float* __restrict__ cbT,       // [128,2048]
    const float* __restrict__ cbnorm,    // [2048]
    const float* __restrict__ cb,        // [2048,128]
    float* __restrict__ quant,           // [65536,128]
    float* __restrict__ disc)            // [65536,2048], pre-zeroed
{
    __shared__ float As[8][128];
    __shared__ float Bs[8][128];
    __shared__ float sval[128][16];
    __shared__ int   sidx[128][16];
    __shared__ int   srow[128];

    int tid = threadIdx.x;
    int tx = tid & 15;
    int ty = tid >> 4;
    long bm = (long)blockIdx.x * 128;

    int arow = tid >> 1, acol = (tid & 1) * 4;
    int wrow = tid >> 5, wcol = (tid & 31) * 4;

    float bestv[8];
    int   besti[8];
    #pragma unroll
    for (int i = 0; i < 8; i++) { bestv[i] = 3.4e38f; besti[i] = 0; }

    const float* Abase = flat + (bm + arow) * EE + acol;

    for (int nt = 0; nt < 16; nt++) {
        int bn = nt * 128;
        float acc[8][8];
        #pragma unroll
        for (int i = 0; i < 8; i++)
            #pragma unroll
            for (int j = 0; j < 8; j++) acc[i][j] = 0.f;

        #pragma unroll
        for (int k0 = 0; k0 < 128; k0 += 8) {
            float4 av = *(const float4*)(Abase + k0);
            float4 wv = *(const float4*)(cbT + (long)(k0 + wrow) * KCB + bn + wcol);
            As[acol + 0][arow] = av.x;
            As[acol + 1][arow] = av.y;
            As[acol + 2][arow] = av.z;
            As[acol + 3][arow] = av.w;
            *(float4*)&Bs[wrow][wcol] = wv;
            __syncthreads();
            #pragma unroll
            for (int kk = 0; kk < 8; kk++) {
                float a0[4], a1[4], b0[4], b1[4];
                *(float4*)a0 = *(const float4*)&As[kk][ty * 4];
                *(float4*)a1 = *(const float4*)&As[kk][64 + ty * 4];
                *(float4*)b0 = *(const float4*)&Bs[kk][tx * 4];
                *(float4*)b1 = *(const float4*)&Bs[kk][64 + tx * 4];
                #pragma unroll
                for (int i = 0; i < 4; i++)
                    #pragma unroll
                    for (int j = 0; j < 4; j++) {
                        acc[i    ][j    ] += a0[i] * b0[j];
                        acc[i    ][j + 4] += a0[i] * b1[j];
                        acc[i + 4][j    ] += a1[i] * b0[j];
                        acc[i + 4][j + 4] += a1[i] * b1[j];
                    }
            }
            __syncthreads();
        }

        float n0[4], n1[4];
        #pragma unroll
        for (int j = 0; j < 4; j++) {
            n0[j] = __ldg(&cbnorm[bn + tx * 4 + j]);
            n1[j] = __ldg(&cbnorm[bn + 64 + tx * 4 + j]);
        }
        #pragma unroll
        for (int i = 0; i < 8; i++) {
            #pragma unroll
            for (int j = 0; j < 4; j++) {          // ascending index within thread
                float d = n0[j] - 2.f * acc[i][j];
                if (d < bestv[i]) { bestv[i] = d; besti[i] = bn + tx * 4 + j; }
            }
            #pragma unroll
            for (int j = 0; j < 4; j++) {
                float d = n1[j] - 2.f * acc[i][j + 4];
                if (d < bestv[i]) { bestv[i] = d; besti[i] = bn + 64 + tx * 4 + j; }
            }
        }
    }

    #pragma unroll
    for (int i = 0; i < 8; i++) {
        int r = (i < 4) ? (ty * 4 + i) : (64 + ty * 4 + i - 4);
        sval[r][tx] = bestv[i];
        sidx[r][tx] = besti[i];
    }
    __syncthreads();

    if (tid < 128) {
        int r = tid;
        float bv = sval[r][0];
        int   bi = sidx[r][0];
        #pragma unroll
        for (int t = 1; t < 16; t++) {
            float v = sval[r][t];
            int  ix = sidx[r][t];
            if (v < bv || (v == bv && ix < bi)) { bv = v; bi = ix; }
        }
        srow[r] = bi;
        disc[(bm + r) * (long)KCB + bi] = 1.0f;   // one-hot scatter
    }
    __syncthreads();

    // quantized = codebook[idx] : 128 rows x 32 float4
    for (int it = tid; it < 128 * 32; it += 256) {
        int r = it >> 5, c = it & 31;
        float4 v = ((const float4*)cb)[srow[r] * 32 + c];
        ((float4*)quant)[(bm + r) * 32 + c] = v;
    }
}

// ---------------------------------------------------------------------------
extern "C" void kernel_launch(void* const* d_in, const int* in_sizes, int n_in,
                              void* d_out, int out_size) {
    const float* cond = (const float*)d_in[0];
    const float* cb   = (const float*)d_in[1];
    const float* We1  = (const float*)d_in[2];  const float* be1 = (const float*)d_in[3];
    const float* We2  = (const float*)d_in[4];  const float* be2 = (const float*)d_in[5];
    const float* We3  = (const float*)d_in[6];  const float* be3 = (const float*)d_in[7];
    const float* We4  = (const float*)d_in[8];  const float* be4 = (const float*)d_in[9];
    const float* Wd1  = (const float*)d_in[10]; const float* bd1 = (const float*)d_in[11];
    const float* Wd2  = (const float*)d_in[12]; const float* bd2 = (const float*)d_in[13];
    const float* Wd3  = (const float*)d_in[14]; const float* bd3 = (const float*)d_in[15];
    const float* Wd4  = (const float*)d_in[16]; const float* bd4 = (const float*)d_in[17];

    float* out   = (float*)d_out;
    float* recon = out;                                  // [4096,256]
    float* enc   = recon + (long)BQ * 256;               // [4096,2048]
    float* disc  = enc   + (long)BQ * LE;                // [65536,2048]
    float* quant = disc  + (long)NROWS * KCB;            // [4096,2048]

    float *x1, *a, *b, *cbT, *cbn;
    cudaGetSymbolAddress((void**)&x1,  g_x1);
    cudaGetSymbolAddress((void**)&a,   g_a);
    cudaGetSymbolAddress((void**)&b,   g_b);
    cudaGetSymbolAddress((void**)&cbT, g_cbT);
    cudaGetSymbolAddress((void**)&cbn, g_cbnorm);

    // codebook transpose + norms
    cbprep_kernel<<<KCB, 128>>>(cb, cbT, cbn);

    // encoder
    dense_lrelu_kernel<<<dim3(1, 32),  256>>>(cond, We1, be1, x1,  BQ, EE, 256);
    dense_lrelu_kernel<<<dim3(16, 32), 256>>>(x1,   We2, be2, a,   BQ, LE, EE);
    dense_lrelu_kernel<<<dim3(16, 32), 256>>>(a,    We3, be3, b,   BQ, LE, LE);
    dense_lrelu_kernel<<<dim3(16, 32), 256>>>(b,    We4, be4, enc, BQ, LE, LE);

    // zero one-hot region, then VQ
    zero_kernel<<<8192, 256>>>((float4*)disc, (long)NROWS * KCB / 4);
    vq_kernel<<<NROWS / 128, 256>>>(enc, cbT, cbn, cb, quant, disc);

    // decoder (reads quantized from d_out)
    dense_lrelu_kernel<<<dim3(16, 32), 256>>>(quant, Wd1, bd1, a,     BQ, LE, LE);
    dense_lrelu_kernel<<<dim3(16, 32), 256>>>(a,     Wd2, bd2, b,     BQ, LE, LE);
    dense_lrelu_kernel<<<dim3(1, 32),  256>>>(b,     Wd3, bd3, x1,    BQ, EE, LE);
    dense_lrelu_kernel<<<dim3(2, 32),  256>>>(x1,    Wd4, bd4, recon, BQ, 256, EE);
}

// round 2
// speedup vs baseline: 1.1188x; 1.1188x over previous
#include <cuda_runtime.h>
#include <cuda_bf16.h>

// ---------------------------------------------------------------------------
// VQ-VAE forward, fp32 with FFMA2 (fma.rn.f32x2) + cp.async double buffering.
// Shapes: B=4096, COND=256, E=128, L=16 (L*E=2048), Kcb=2048, P=256.
// Outputs in d_out: recon[4096*256], encoded[4096*2048],
// discrete[65536*2048], quantized[4096*2048].
// ---------------------------------------------------------------------------

#define BQ 4096
#define LE 2048
#define EE 128
#define KCB 2048
#define NROWS 65536   // B*L

// scratch (device globals; allocation-free rule)
__device__ float g_x1[BQ * EE];          // 2 MB (x1 / y3 reuse)
__device__ float g_a [BQ * LE];          // 32 MB
__device__ float g_b [BQ * LE];          // 32 MB
__device__ float g_cbT[EE * KCB];        // 1 MB
__device__ float g_cbnorm[KCB];

__device__ __forceinline__ float lrelu(float v) {
    return fmaxf(v, 0.2f * v);   // slope 0.2 < 1 so exact
}

// ---- packed fp32x2 helpers -------------------------------------------------
__device__ __forceinline__ unsigned long long pack2(float lo, float hi) {
    unsigned long long r;
    asm("mov.b64 %0, {%1, %2};" : "=l"(r) : "f"(lo), "f"(hi));
    return r;
}
__device__ __forceinline__ void fma2(unsigned long long& acc,
                                     unsigned long long a, unsigned long long b) {
    asm("fma.rn.f32x2 %0, %1, %2, %0;" : "+l"(acc) : "l"(a), "l"(b));
}
__device__ __forceinline__ float2 unpack2(unsigned long long v) {
    float lo, hi;
    asm("mov.b64 {%0, %1}, %2;" : "=f"(lo), "=f"(hi) : "l"(v));
    return make_float2(lo, hi);
}

// ---- cp.async helpers ------------------------------------------------------
__device__ __forceinline__ void cp_async16(void* smem, const void* gmem) {
    unsigned s = (unsigned)__cvta_generic_to_shared(smem);
    asm volatile("cp.async.cg.shared.global [%0], [%1], 16;\n" :: "r"(s), "l"(gmem));
}
__device__ __forceinline__ void cp_commit() {
    asm volatile("cp.async.commit_group;\n");
}
template<int N> __device__ __forceinline__ void cp_wait() {
    asm volatile("cp.async.wait_group %0;\n" :: "n"(N));
}

// ---------------------------------------------------------------------------
// codebook prep: transpose [2048,128] -> [128,2048] and row norms
// ---------------------------------------------------------------------------
__global__ void cbprep_kernel(const float* __restrict__ cb,
                              float* __restrict__ cbT,
                              float* __restrict__ cbnorm) {
    int n = blockIdx.x;       // 0..2047
    int e = threadIdx.x;      // 0..127
    float v = cb[n * EE + e];
    cbT[e * KCB + n] = v;
    float s = v * v;
    #pragma unroll
    for (int off = 16; off > 0; off >>= 1)
        s += __shfl_xor_sync(0xFFFFFFFFu, s, off);
    __shared__ float ws[4];
    if ((e & 31) == 0) ws[e >> 5] = s;
    __syncthreads();
    if (e == 0) cbnorm[n] = ws[0] + ws[1] + ws[2] + ws[3];
}

// ---------------------------------------------------------------------------
// Dense + LeakyReLU, 128x128 tile, BK=8, FFMA2, cp.async double buffer.
// ---------------------------------------------------------------------------
__global__ __launch_bounds__(256, 2) void dense_lrelu_128(
    const float* __restrict__ A, const float* __restrict__ W,
    const float* __restrict__ bias, float* __restrict__ C,
    int M, int N, int K)
{
    __shared__ float As[2][8][128];
    __shared__ float Bs[2][8][128];

    int tid = threadIdx.x;
    int tx = tid & 15;
    int ty = tid >> 4;
    int bm = blockIdx.y * 128;
    int bn = blockIdx.x * 128;

    int arow = tid >> 1;          // 0..127
    int acol = (tid & 1) * 4;     // 0 or 4
    int wrow = tid >> 5;          // 0..7
    int wcol = (tid & 31) * 4;    // 0..124

    unsigned long long acc[8][4];
    #pragma unroll
    for (int i = 0; i < 8; i++)
        #pragma unroll
        for (int j = 0; j < 4; j++) acc[i][j] = 0ULL;

    const float* Ap = A + (long)(bm + arow) * K + acol;
    const float* Wp = W + (long)wrow * N + bn + wcol;
    long wstep = (long)8 * N;

    int T = K >> 3;
    float4 areg = *(const float4*)Ap;  Ap += 8;
    cp_async16(&Bs[0][wrow][wcol], Wp); Wp += wstep;
    cp_commit();

    for (int i = 0; i < T; i++) {
        int cur = i & 1;
        As[cur][acol + 0][arow] = areg.x;
        As[cur][acol + 1][arow] = areg.y;
        As[cur][acol + 2][arow] = areg.z;
        As[cur][acol + 3][arow] = areg.w;
        if (i + 1 < T) {
            areg = *(const float4*)Ap;  Ap += 8;
            cp_async16(&Bs[cur ^ 1][wrow][wcol], Wp); Wp += wstep;
            cp_commit();
            cp_wait<1>();
        } else {
            cp_wait<0>();
        }
        __syncthreads();
        #pragma unroll
        for (int kk = 0; kk < 8; kk++) {
            float4 a0 = *(const float4*)&As[cur][kk][ty * 4];
            float4 a1 = *(const float4*)&As[cur][kk][64 + ty * 4];
            float4 b0 = *(const float4*)&Bs[cur][kk][tx * 4];
            float4 b1 = *(const float4*)&Bs[cur][kk][64 + tx * 4];
            unsigned long long bp[4] = { pack2(b0.x, b0.y), pack2(b0.z, b0.w),
                                         pack2(b1.x, b1.y), pack2(b1.z, b1.w) };
            float av[8] = {a0.x, a0.y, a0.z, a0.w, a1.x, a1.y, a1.z, a1.w};
            #pragma unroll
            for (int r = 0; r < 8; r++) {
                unsigned long long ap = pack2(av[r], av[r]);
                fma2(acc[r][0], ap, bp[0]);
                fma2(acc[r][1], ap, bp[1]);
                fma2(acc[r][2], ap, bp[2]);
                fma2(acc[r][3], ap, bp[3]);
            }
        }
        __syncthreads();
    }

    float bb0[4], bb1[4];
    #pragma unroll
    for (int j = 0; j < 4; j++) {
        bb0[j] = __ldg(&bias[bn + tx * 4 + j]);
        bb1[j] = __ldg(&bias[bn + 64 + tx * 4 + j]);
    }
    #pragma unroll
    for (int i = 0; i < 8; i++) {
        int r = bm + ((i < 4) ? (ty * 4 + i) : (64 + ty * 4 + i - 4));
        float2 p0 = unpack2(acc[i][0]);
        float2 p1 = unpack2(acc[i][1]);
        float2 p2 = unpack2(acc[i][2]);
        float2 p3 = unpack2(acc[i][3]);
        float4 o;
        o.x = lrelu(p0.x + bb0[0]);
        o.y = lrelu(p0.y + bb0[1]);
        o.z = lrelu(p1.x + bb0[2]);
        o.w = lrelu(p1.y + bb0[3]);
        *(float4*)&C[(long)r * N + bn + tx * 4] = o;
        o.x = lrelu(p2.x + bb1[0]);
        o.y = lrelu(p2.y + bb1[1]);
        o.z = lrelu(p3.x + bb1[2]);
        o.w = lrelu(p3.y + bb1[3]);
        *(float4*)&C[(long)r * N + bn + 64 + tx * 4] = o;
    }
}

// ---------------------------------------------------------------------------
// Dense + LeakyReLU, 32x128 tile (skinny layers), FFMA2, cp.async on B.
// ---------------------------------------------------------------------------
__global__ __launch_bounds__(256) void dense_lrelu_32(
    const float* __restrict__ A, const float* __restrict__ W,
    const float* __restrict__ bias, float* __restrict__ C,
    int M, int N, int K)
{
    __shared__ float As[2][8][32];
    __shared__ float Bs[2][8][128];

    int tid = threadIdx.x;
    int tx = tid & 15;
    int ty = tid >> 4;            // 0..15 -> rows ty*2, ty*2+1
    int bm = blockIdx.y * 32;
    int bn = blockIdx.x * 128;

    int arow = tid >> 3;          // 0..31
    int acol = tid & 7;           // 0..7
    int wrow = tid >> 5;
    int wcol = (tid & 31) * 4;

    unsigned long long acc[2][4];
    #pragma unroll
    for (int i = 0; i < 2; i++)
        #pragma unroll
        for (int j = 0; j < 4; j++) acc[i][j] = 0ULL;

    const float* Ap = A + (long)(bm + arow) * K + acol;
    const float* Wp = W + (long)wrow * N + bn + wcol;
    long wstep = (long)8 * N;

    int T = K >> 3;
    float areg = *Ap;  Ap += 8;
    cp_async16(&Bs[0][wrow][wcol], Wp); Wp += wstep;
    cp_commit();

    for (int i = 0; i < T; i++) {
        int cur = i & 1;
        As[cur][acol][arow] = areg;
        if (i + 1 < T) {
            areg = *Ap;  Ap += 8;
            cp_async16(&Bs[cur ^ 1][wrow][wcol], Wp); Wp += wstep;
            cp_commit();
            cp_wait<1>();
        } else {
            cp_wait<0>();
        }
        __syncthreads();
        #pragma unroll
        for (int kk = 0; kk < 8; kk++) {
            float2 a2 = *(const float2*)&As[cur][kk][ty * 2];
            float4 b0 = *(const float4*)&Bs[cur][kk][tx * 4];
            float4 b1 = *(const float4*)&Bs[cur][kk][64 + tx * 4];
            unsigned long long bp[4] = { pack2(b0.x, b0.y), pack2(b0.z, b0.w),
                                         pack2(b1.x, b1.y), pack2(b1.z, b1.w) };
            unsigned long long ap0 = pack2(a2.x, a2.x);
            unsigned long long ap1 = pack2(a2.y, a2.y);
            fma2(acc[0][0], ap0, bp[0]); fma2(acc[0][1], ap0, bp[1]);
            fma2(acc[0][2], ap0, bp[2]); fma2(acc[0][3], ap0, bp[3]);
            fma2(acc[1][0], ap1, bp[0]); fma2(acc[1][1], ap1, bp[1]);
            fma2(acc[1][2], ap1, bp[2]); fma2(acc[1][3], ap1, bp[3]);
        }
        __syncthreads();
    }

    float bb0[4], bb1[4];
    #pragma unroll
    for (int j = 0; j < 4; j++) {
        bb0[j] = __ldg(&bias[bn + tx * 4 + j]);
        bb1[j] = __ldg(&bias[bn + 64 + tx * 4 + j]);
    }
    #pragma unroll
    for (int i = 0; i < 2; i++) {
        int r = bm + ty * 2 + i;
        float2 p0 = unpack2(acc[i][0]);
        float2 p1 = unpack2(acc[i][1]);
        float2 p2 = unpack2(acc[i][2]);
        float2 p3 = unpack2(acc[i][3]);
        float4 o;
        o.x = lrelu(p0.x + bb0[0]);
        o.y = lrelu(p0.y + bb0[1]);
        o.z = lrelu(p1.x + bb0[2]);
        o.w = lrelu(p1.y + bb0[3]);
        *(float4*)&C[(long)r * N + bn + tx * 4] = o;
        o.x = lrelu(p2.x + bb1[0]);
        o.y = lrelu(p2.y + bb1[1]);
        o.z = lrelu(p3.x + bb1[2]);
        o.w = lrelu(p3.y + bb1[3]);
        *(float4*)&C[(long)r * N + bn + 64 + tx * 4] = o;
    }
}

// ---------------------------------------------------------------------------
// VQ: per 128-row block: scores over all 2048 codewords (FFMA2 GEMM),
// argmin with first-index tie semantics, one-hot slab write (incl zeros),
// quantized gather.
// ---------------------------------------------------------------------------
__global__ __launch_bounds__(256, 2) void vq_kernel(
    const float* __restrict__ flat,      // [65536,128]
    const float* __restrict__ cbT,       // [128,2048]
    const float* __restrict__ cbnorm,    // [2048]
    const float* __restrict__ cb,        // [2048,128]
    float* __restrict__ quant,           // [65536,128]
    float* __restrict__ disc)            // [65536,2048]
{
    __shared__ float As[2][8][128];
    __shared__ float Bs[2][8][128];
    __shared__ float sval[128][16];
    __shared__ int   sidx[128][16];
    __shared__ int   srow[128];

    int tid = threadIdx.x;
    int tx = tid & 15;
    int ty = tid >> 4;
    long bm = (long)blockIdx.x * 128;

    int arow = tid >> 1, acol = (tid & 1) * 4;
    int wrow = tid >> 5, wcol = (tid & 31) * 4;

    float bestv[8];
    int   besti[8];
    #pragma unroll
    for (int i = 0; i < 8; i++) { bestv[i] = 3.4e38f; besti[i] = 0; }

    const float* Abase = flat + (bm + arow) * EE + acol;

    for (int nt = 0; nt < 16; nt++) {
        int bn = nt * 128;
        unsigned long long acc[8][4];
        #pragma unroll
        for (int i = 0; i < 8; i++)
            #pragma unroll
            for (int j = 0; j < 4; j++) acc[i][j] = 0ULL;

        const float* Ap = Abase;
        const float* Wp = cbT + (long)wrow * KCB + bn + wcol;

        float4 areg = *(const float4*)Ap;  Ap += 8;
        cp_async16(&Bs[0][wrow][wcol], Wp); Wp += 8 * KCB;
        cp_commit();

        #pragma unroll 1
        for (int i = 0; i < 16; i++) {
            int cur = i & 1;
            As[cur][acol + 0][arow] = areg.x;
            As[cur][acol + 1][arow] = areg.y;
            As[cur][acol + 2][arow] = areg.z;
            As[cur][acol + 3][arow] = areg.w;
            if (i + 1 < 16) {
                areg = *(const float4*)Ap;  Ap += 8;
                cp_async16(&Bs[cur ^ 1][wrow][wcol], Wp); Wp += 8 * KCB;
                cp_commit();
                cp_wait<1>();
            } else {
                cp_wait<0>();
            }
            __syncthreads();
            #pragma unroll
            for (int kk = 0; kk < 8; kk++) {
                float4 a0 = *(const float4*)&As[cur][kk][ty * 4];
                float4 a1 = *(const float4*)&As[cur][kk][64 + ty * 4];
                float4 b0 = *(const float4*)&Bs[cur][kk][tx * 4];
                float4 b1 = *(const float4*)&Bs[cur][kk][64 + tx * 4];
                unsigned long long bp[4] = { pack2(b0.x, b0.y), pack2(b0.z, b0.w),
                                             pack2(b1.x, b1.y), pack2(b1.z, b1.w) };
                float av[8] = {a0.x, a0.y, a0.z, a0.w, a1.x, a1.y, a1.z, a1.w};
                #pragma unroll
                for (int r = 0; r < 8; r++) {
                    unsigned long long ap = pack2(av[r], av[r]);
                    fma2(acc[r][0], ap, bp[0]);
                    fma2(acc[r][1], ap, bp[1]);
                    fma2(acc[r][2], ap, bp[2]);
                    fma2(acc[r][3], ap, bp[3]);
                }
            }
            __syncthreads();
        }

        float n0[4], n1[4];
        #pragma unroll
        for (int j = 0; j < 4; j++) {
            n0[j] = __ldg(&cbnorm[bn + tx * 4 + j]);
            n1[j] = __ldg(&cbnorm[bn + 64 + tx * 4 + j]);
        }
        #pragma unroll
        for (int i = 0; i < 8; i++) {
            float2 p0 = unpack2(acc[i][0]);
            float2 p1 = unpack2(acc[i][1]);
            float2 p2 = unpack2(acc[i][2]);
            float2 p3 = unpack2(acc[i][3]);
            float v[8] = {p0.x, p0.y, p1.x, p1.y, p2.x, p2.y, p3.x, p3.y};
            #pragma unroll
            for (int j = 0; j < 4; j++) {   // ascending index order
                float d = n0[j] - 2.f * v[j];
                if (d < bestv[i]) { bestv[i] = d; besti[i] = bn + tx * 4 + j; }
            }
            #pragma unroll
            for (int j = 0; j < 4; j++) {
                float d = n1[j] - 2.f * v[4 + j];
                if (d < bestv[i]) { bestv[i] = d; besti[i] = bn + 64 + tx * 4 + j; }
            }
        }
    }

    #pragma unroll
    for (int i = 0; i < 8; i++) {
        int r = (i < 4) ? (ty * 4 + i) : (64 + ty * 4 + i - 4);
        sval[r][tx] = bestv[i];
        sidx[r][tx] = besti[i];
    }
    __syncthreads();

    if (tid < 128) {
        int r = tid;
        float bv = sval[r][0];
        int   bi = sidx[r][0];
        #pragma unroll
        for (int t = 1; t < 16; t++) {
            float v = sval[r][t];
            int  ix = sidx[r][t];
            if (v < bv || (v == bv && ix < bi)) { bv = v; bi = ix; }
        }
        srow[r] = bi;
    }
    __syncthreads();

    // one-hot slab (zeros + 1.0), 128 rows x 512 float4
    for (int it = tid; it < 128 * 512; it += 256) {
        int r = it >> 9;
        int c4 = it & 511;
        float4 z = make_float4(0.f, 0.f, 0.f, 0.f);
        int bi = srow[r];
        if ((bi >> 2) == c4) ((float*)&z)[bi & 3] = 1.0f;
        ((float4*)disc)[(bm + r) * 512 + c4] = z;
    }

    // quantized = codebook[idx]
    for (int it = tid; it < 128 * 32; it += 256) {
        int r = it >> 5, c = it & 31;
        float4 v = ((const float4*)cb)[srow[r] * 32 + c];
        ((float4*)quant)[(bm + r) * 32 + c] = v;
    }
}

// ---------------------------------------------------------------------------
extern "C" void kernel_launch(void* const* d_in, const int* in_sizes, int n_in,
                              void* d_out, int out_size) {
    const float* cond = (const float*)d_in[0];
    const float* cb   = (const float*)d_in[1];
    const float* We1  = (const float*)d_in[2];  const float* be1 = (const float*)d_in[3];
    const float* We2  = (const float*)d_in[4];  const float* be2 = (const float*)d_in[5];
    const float* We3  = (const float*)d_in[6];  const float* be3 = (const float*)d_in[7];
    const float* We4  = (const float*)d_in[8];  const float* be4 = (const float*)d_in[9];
    const float* Wd1  = (const float*)d_in[10]; const float* bd1 = (const float*)d_in[11];
    const float* Wd2  = (const float*)d_in[12]; const float* bd2 = (const float*)d_in[13];
    const float* Wd3  = (const float*)d_in[14]; const float* bd3 = (const float*)d_in[15];
    const float* Wd4  = (const float*)d_in[16]; const float* bd4 = (const float*)d_in[17];

    float* out   = (float*)d_out;
    float* recon = out;                                  // [4096,256]
    float* enc   = recon + (long)BQ * 256;               // [4096,2048]
    float* disc  = enc   + (long)BQ * LE;                // [65536,2048]
    float* quant = disc  + (long)NROWS * KCB;            // [4096,2048]

    float *x1, *a, *b, *cbT, *cbn;
    cudaGetSymbolAddress((void**)&x1,  g_x1);
    cudaGetSymbolAddress((void**)&a,   g_a);
    cudaGetSymbolAddress((void**)&b,   g_b);
    cudaGetSymbolAddress((void**)&cbT, g_cbT);
    cudaGetSymbolAddress((void**)&cbn, g_cbnorm);

    // codebook transpose + norms
    cbprep_kernel<<<KCB, 128>>>(cb, cbT, cbn);

    // encoder
    dense_lrelu_32 <<<dim3(1, 128), 256>>>(cond, We1, be1, x1,  BQ, EE, 256);
    dense_lrelu_128<<<dim3(16, 32), 256>>>(x1,   We2, be2, a,   BQ, LE, EE);
    dense_lrelu_128<<<dim3(16, 32), 256>>>(a,    We3, be3, b,   BQ, LE, LE);
    dense_lrelu_128<<<dim3(16, 32), 256>>>(b,    We4, be4, enc, BQ, LE, LE);

    // VQ (writes full one-hot slab itself)
    vq_kernel<<<NROWS / 128, 256>>>(enc, cbT, cbn, cb, quant, disc);

    // decoder
    dense_lrelu_128<<<dim3(16, 32), 256>>>(quant, Wd1, bd1, a,     BQ, LE, LE);
    dense_lrelu_128<<<dim3(16, 32), 256>>>(a,     Wd2, bd2, b,     BQ, LE, LE);
    dense_lrelu_32 <<<dim3(1, 128), 256>>>(b,     Wd3, bd3, x1,    BQ, EE, LE);
    dense_lrelu_32 <<<dim3(2, 128), 256>>>(x1,    Wd4, bd4, recon, BQ, 256, EE);
}